// round 5
// baseline (speedup 1.0000x reference)
#include <cuda_runtime.h>
#include <cstdint>

#define NEG_SLOPE 0.2f

static const int NMAX = 50000;
static const int EMAX = 800000;

// ---------------- scratch ---------------------------------------------------
__device__ __align__(16) float g_h1[NMAX * 128];
__device__ __align__(16) float g_out1[NMAX * 128];
__device__ __align__(16) float g_h2[NMAX * 40];
__device__ __align__(16) float g_asrc1[NMAX * 8];
__device__ __align__(16) float g_adst1[NMAX * 8];
__device__ __align__(16) float g_asrc2[NMAX];
__device__ __align__(16) float g_adst2[NMAX];
__device__ __align__(16) uint32_t g_w1p[2 * 16 * 8 * 68];   // permuted tf32 W1
__device__ int g_cnt[NMAX];
__device__ int g_off[NMAX + 1];
__device__ int g_cursor[NMAX];
__device__ int g_csr[EMAX];

__device__ __forceinline__ float lrelu(float v) { return v > 0.f ? v : NEG_SLOPE * v; }
__device__ __forceinline__ uint32_t f2tf32(float f) {
    uint32_t u;
    asm("cvt.rna.tf32.f32 %0, %1;" : "=r"(u) : "f"(f));
    return u;
}

// ---------------- W1 prep: convert to tf32 + permute to fragment order ------
// storage slot g*8+nt (within [half][kt][kq] row, stride 68) must hold
// column nt*8+g of that half  =>  for column c = n&63 store at (c&7)*8+(c>>3).
__global__ void prep_w1_kernel(const float* __restrict__ W) {
    int i = blockIdx.x * 256 + threadIdx.x;
    if (i >= 128 * 128) return;
    int k = i >> 7, n = i & 127;
    int half = n >> 6, kt = k >> 3, kq = k & 7;
    int c = n & 63;
    int slot = (c & 7) * 8 + (c >> 3);   // transpose: slot(g,nt) holds col nt*8+g
    g_w1p[((half * 16 + kt) * 8 + kq) * 68 + slot] = f2tf32(W[k * 128 + n]);
}

// ---------------- CSR build -------------------------------------------------
__global__ void hist_kernel(const int* __restrict__ dst, int E) {
    int e4 = blockIdx.x * blockDim.x + threadIdx.x;
    if (e4 * 4 + 3 < E) {
        int4 d = ((const int4*)dst)[e4];
        atomicAdd(&g_cnt[d.x], 1);
        atomicAdd(&g_cnt[d.y], 1);
        atomicAdd(&g_cnt[d.z], 1);
        atomicAdd(&g_cnt[d.w], 1);
    } else {
        for (int e = e4 * 4; e < E; e++) atomicAdd(&g_cnt[dst[e]], 1);
    }
}

__global__ void scan_kernel(int n) {
    __shared__ int wsum[32];
    int tid = threadIdx.x;
    int lane = tid & 31, w = tid >> 5;
    int chunk = (n + 1023) >> 10;
    int beg = tid * chunk;
    int end = min(beg + chunk, n);
    int s = 0;
    for (int i = beg; i < end; i++) s += g_cnt[i];
    int v = s;
#pragma unroll
    for (int o = 1; o < 32; o <<= 1) {
        int t = __shfl_up_sync(0xffffffffu, v, o);
        if (lane >= o) v += t;
    }
    if (lane == 31) wsum[w] = v;
    __syncthreads();
    if (w == 0) {
        int x = wsum[lane];
#pragma unroll
        for (int o = 1; o < 32; o <<= 1) {
            int t = __shfl_up_sync(0xffffffffu, x, o);
            if (lane >= o) x += t;
        }
        wsum[lane] = x;
    }
    __syncthreads();
    int run = v - s + (w ? wsum[w - 1] : 0);
    for (int i = beg; i < end; i++) {
        int c = g_cnt[i];
        g_off[i] = run;
        run += c;
    }
    if (tid == 1023) g_off[n] = run;
}

__global__ void scatter_kernel(const int* __restrict__ src,
                               const int* __restrict__ dst, int E) {
    int e = blockIdx.x * blockDim.x + threadIdx.x;
    if (e < E) {
        int d = dst[e];
        int pos = atomicAdd(&g_cursor[d], 1);
        g_csr[pos] = src[e];
    }
}

// ---------------- layer1 GEMM: TF32 mma + fused attention logits ------------
__global__ __launch_bounds__(256) void gemm1_tf32_kernel(
    const float* __restrict__ X,
    const float* __restrict__ att_src, const float* __restrict__ att_dst,
    float* __restrict__ Y, int N) {
    const int XS = 132;
    extern __shared__ float smf[];
    uint32_t* ws = (uint32_t*)smf;                  // 17408 u32 (permuted tf32 W)
    uint32_t* xs = (uint32_t*)(smf + 17408);        // 64 x XS
    float* satt = smf + 17408 + 64 * XS;            // 256 floats
    int tid = threadIdx.x;

    for (int i = tid; i < 17408 / 4; i += 256)
        ((uint4*)ws)[i] = ((const uint4*)g_w1p)[i];
    satt[tid] = (tid < 128) ? att_src[tid] : att_dst[tid - 128];

    int row0 = blockIdx.x * 64;
    for (int i = tid; i < 64 * 32; i += 256) {
        int r = i >> 5, k4 = (i & 31) * 4;
        int row = row0 + r;
        float4 v = (row < N) ? *(const float4*)&X[row * 128 + k4]
                             : make_float4(0.f, 0.f, 0.f, 0.f);
        uint32_t* p = &xs[r * XS + k4];
        p[0] = f2tf32(v.x); p[1] = f2tf32(v.y); p[2] = f2tf32(v.z); p[3] = f2tf32(v.w);
    }
    __syncthreads();

    int lane = tid & 31, wid = tid >> 5;
    int wm = (wid >> 1) * 16;
    int wn = (wid & 1) * 64;
    int q = lane & 3, g = lane >> 2;
    int half = wn >> 6;

    float c[8][4];
#pragma unroll
    for (int nt = 0; nt < 8; nt++)
#pragma unroll
        for (int j = 0; j < 4; j++) c[nt][j] = 0.f;

#pragma unroll
    for (int kt = 0; kt < 16; kt++) {
        int k0 = kt * 8;
        int ar = wm + g;
        uint32_t a0 = xs[ar * XS + k0 + q];
        uint32_t a1 = xs[(ar + 8) * XS + k0 + q];
        uint32_t a2 = xs[ar * XS + k0 + q + 4];
        uint32_t a3 = xs[(ar + 8) * XS + k0 + q + 4];
        const uint32_t* wp = ws + (half * 16 + kt) * 8 * 68;
        uint4 b0lo = *(const uint4*)&wp[q * 68 + g * 8];
        uint4 b0hi = *(const uint4*)&wp[q * 68 + g * 8 + 4];
        uint4 b1lo = *(const uint4*)&wp[(q + 4) * 68 + g * 8];
        uint4 b1hi = *(const uint4*)&wp[(q + 4) * 68 + g * 8 + 4];
        uint32_t b0v[8] = {b0lo.x, b0lo.y, b0lo.z, b0lo.w, b0hi.x, b0hi.y, b0hi.z, b0hi.w};
        uint32_t b1v[8] = {b1lo.x, b1lo.y, b1lo.z, b1lo.w, b1hi.x, b1hi.y, b1hi.z, b1hi.w};
#pragma unroll
        for (int nt = 0; nt < 8; nt++) {
            asm volatile(
                "mma.sync.aligned.m16n8k8.row.col.f32.tf32.tf32.f32 "
                "{%0,%1,%2,%3},{%4,%5,%6,%7},{%8,%9},{%0,%1,%2,%3};"
                : "+f"(c[nt][0]), "+f"(c[nt][1]), "+f"(c[nt][2]), "+f"(c[nt][3])
                : "r"(a0), "r"(a1), "r"(a2), "r"(a3), "r"(b0v[nt]), "r"(b1v[nt]));
        }
    }

    int r_lo = row0 + wm + g;
    int r_hi = r_lo + 8;
    float ps_lo[4] = {0, 0, 0, 0}, pd_lo[4] = {0, 0, 0, 0};
    float ps_hi[4] = {0, 0, 0, 0}, pd_hi[4] = {0, 0, 0, 0};
#pragma unroll
    for (int nt = 0; nt < 8; nt++) {
        int col = wn + nt * 8 + 2 * q;
        float as0 = satt[col], as1 = satt[col + 1];
        float ad0 = satt[128 + col], ad1 = satt[128 + col + 1];
        int lh = nt >> 1;
        ps_lo[lh] += c[nt][0] * as0 + c[nt][1] * as1;
        pd_lo[lh] += c[nt][0] * ad0 + c[nt][1] * ad1;
        ps_hi[lh] += c[nt][2] * as0 + c[nt][3] * as1;
        pd_hi[lh] += c[nt][2] * ad0 + c[nt][3] * ad1;
        if (r_lo < N) *(float2*)&Y[r_lo * 128 + col] = make_float2(c[nt][0], c[nt][1]);
        if (r_hi < N) *(float2*)&Y[r_hi * 128 + col] = make_float2(c[nt][2], c[nt][3]);
    }
#pragma unroll
    for (int lh = 0; lh < 4; lh++) {
#pragma unroll
        for (int o = 1; o <= 2; o <<= 1) {
            ps_lo[lh] += __shfl_xor_sync(0xffffffffu, ps_lo[lh], o);
            pd_lo[lh] += __shfl_xor_sync(0xffffffffu, pd_lo[lh], o);
            ps_hi[lh] += __shfl_xor_sync(0xffffffffu, ps_hi[lh], o);
            pd_hi[lh] += __shfl_xor_sync(0xffffffffu, pd_hi[lh], o);
        }
    }
    if (q == 0) {
        int hb = wn >> 4;
#pragma unroll
        for (int lh = 0; lh < 4; lh++) {
            int h = hb + lh;
            if (r_lo < N) { g_asrc1[r_lo * 8 + h] = ps_lo[lh]; g_adst1[r_lo * 8 + h] = pd_lo[lh]; }
            if (r_hi < N) { g_asrc1[r_hi * 8 + h] = ps_hi[lh]; g_adst1[r_hi * 8 + h] = pd_hi[lh]; }
        }
    }
}

// ---------------- layer2 GEMM (TF32) + fused att2 logits --------------------
__global__ __launch_bounds__(256) void gemm2_tf32_kernel(
    const float* __restrict__ X, const float* __restrict__ W,
    const float* __restrict__ att_src, const float* __restrict__ att_dst,
    float* __restrict__ Y, int N) {
    const int WS2 = 44, XS = 132;
    extern __shared__ float smf[];
    uint32_t* ws = (uint32_t*)smf;                   // 128 x WS2
    uint32_t* xs = (uint32_t*)(smf + 128 * WS2);     // 128 x XS
    float* satt = smf + 128 * WS2 + 128 * XS;        // 80 floats
    int tid = threadIdx.x;

    for (int i = tid; i < 128 * 40; i += 256) {
        int k = i / 40, n = i % 40;
        ws[k * WS2 + n] = f2tf32(W[i]);
    }
    if (tid < 40) satt[tid] = att_src[tid];
    else if (tid < 80) satt[tid] = att_dst[tid - 40];

    int row0 = blockIdx.x * 128;
    for (int i = tid; i < 128 * 32; i += 256) {
        int r = i >> 5, k4 = (i & 31) * 4;
        int row = row0 + r;
        float4 v = (row < N) ? *(const float4*)&X[row * 128 + k4]
                             : make_float4(0.f, 0.f, 0.f, 0.f);
        uint32_t* p = &xs[r * XS + k4];
        p[0] = f2tf32(v.x); p[1] = f2tf32(v.y); p[2] = f2tf32(v.z); p[3] = f2tf32(v.w);
    }
    __syncthreads();

    int lane = tid & 31, wid = tid >> 5;
    int wm = wid * 16;
    int q = lane & 3, g = lane >> 2;

    float c[5][4];
#pragma unroll
    for (int nt = 0; nt < 5; nt++)
#pragma unroll
        for (int j = 0; j < 4; j++) c[nt][j] = 0.f;

#pragma unroll
    for (int kt = 0; kt < 16; kt++) {
        int k0 = kt * 8;
        int ar = wm + g;
        uint32_t a0 = xs[ar * XS + k0 + q];
        uint32_t a1 = xs[(ar + 8) * XS + k0 + q];
        uint32_t a2 = xs[ar * XS + k0 + q + 4];
        uint32_t a3 = xs[(ar + 8) * XS + k0 + q + 4];
#pragma unroll
        for (int nt = 0; nt < 5; nt++) {
            uint32_t b0 = ws[(k0 + q) * WS2 + nt * 8 + g];
            uint32_t b1 = ws[(k0 + q + 4) * WS2 + nt * 8 + g];
            asm volatile(
                "mma.sync.aligned.m16n8k8.row.col.f32.tf32.tf32.f32 "
                "{%0,%1,%2,%3},{%4,%5,%6,%7},{%8,%9},{%0,%1,%2,%3};"
                : "+f"(c[nt][0]), "+f"(c[nt][1]), "+f"(c[nt][2]), "+f"(c[nt][3])
                : "r"(a0), "r"(a1), "r"(a2), "r"(a3), "r"(b0), "r"(b1));
        }
    }

    int r_lo = row0 + wm + g;
    int r_hi = r_lo + 8;
    float ps_lo = 0.f, pd_lo = 0.f, ps_hi = 0.f, pd_hi = 0.f;
#pragma unroll
    for (int nt = 0; nt < 5; nt++) {
        int col = nt * 8 + 2 * q;
        float as0 = satt[col], as1 = satt[col + 1];
        float ad0 = satt[40 + col], ad1 = satt[40 + col + 1];
        ps_lo += c[nt][0] * as0 + c[nt][1] * as1;
        pd_lo += c[nt][0] * ad0 + c[nt][1] * ad1;
        ps_hi += c[nt][2] * as0 + c[nt][3] * as1;
        pd_hi += c[nt][2] * ad0 + c[nt][3] * ad1;
        if (r_lo < N) *(float2*)&Y[r_lo * 40 + col] = make_float2(c[nt][0], c[nt][1]);
        if (r_hi < N) *(float2*)&Y[r_hi * 40 + col] = make_float2(c[nt][2], c[nt][3]);
    }
#pragma unroll
    for (int o = 1; o <= 2; o <<= 1) {
        ps_lo += __shfl_xor_sync(0xffffffffu, ps_lo, o);
        pd_lo += __shfl_xor_sync(0xffffffffu, pd_lo, o);
        ps_hi += __shfl_xor_sync(0xffffffffu, ps_hi, o);
        pd_hi += __shfl_xor_sync(0xffffffffu, pd_hi, o);
    }
    if (q == 0) {
        if (r_lo < N) { g_asrc2[r_lo] = ps_lo; g_adst2[r_lo] = pd_lo; }
        if (r_hi < N) { g_asrc2[r_hi] = ps_hi; g_adst2[r_hi] = pd_hi; }
    }
}

// ---------------- aggregation: single-pass online softmax -------------------
__global__ void agg1_kernel(const float* __restrict__ bias, int N) {
    int node = (blockIdx.x * blockDim.x + threadIdx.x) >> 5;
    if (node >= N) return;
    int lane = threadIdx.x & 31;
    int h = lane >> 2;
    int beg = g_off[node], end = g_off[node + 1];

    float adst = g_adst1[node * 8 + h];
    float m = lrelu(g_asrc1[node * 8 + h] + adst);   // self-loop
    float denom = 1.f;
    float4 acc = *(const float4*)&g_h1[node * 128 + lane * 4];

#pragma unroll 2
    for (int e = beg; e < end; e++) {
        int s = g_csr[e];
        float a = lrelu(g_asrc1[s * 8 + h] + adst);
        float4 v = *(const float4*)&g_h1[s * 128 + lane * 4];
        float d = a - m;
        float t = __expf(-fabsf(d));
        bool up = d > 0.f;
        float scale = up ? t : 1.f;
        float wv = up ? 1.f : t;
        m = up ? a : m;
        denom = fmaf(denom, scale, wv);
        acc.x = fmaf(wv, v.x, acc.x * scale);
        acc.y = fmaf(wv, v.y, acc.y * scale);
        acc.z = fmaf(wv, v.z, acc.z * scale);
        acc.w = fmaf(wv, v.w, acc.w * scale);
    }
    float inv = 1.f / (denom + 1e-16f);
    float4 b = *(const float4*)&bias[lane * 4];
    *(float4*)&g_out1[node * 128 + lane * 4] =
        make_float4(fmaf(acc.x, inv, b.x), fmaf(acc.y, inv, b.y),
                    fmaf(acc.z, inv, b.z), fmaf(acc.w, inv, b.w));
}

__global__ void agg2_kernel(const float* __restrict__ bias, float* __restrict__ out, int N) {
    int node = (blockIdx.x * blockDim.x + threadIdx.x) >> 5;
    if (node >= N) return;
    int lane = threadIdx.x & 31;
    int beg = g_off[node], end = g_off[node + 1];

    float adst = g_adst2[node];
    float m = lrelu(g_asrc2[node] + adst);
    float denom = 1.f;
    float4 acc = make_float4(0.f, 0.f, 0.f, 0.f);
    if (lane < 10) acc = *(const float4*)&g_h2[node * 40 + lane * 4];

#pragma unroll 2
    for (int e = beg; e < end; e++) {
        int s = g_csr[e];
        float a = lrelu(g_asrc2[s] + adst);
        float d = a - m;
        float t = __expf(-fabsf(d));
        bool up = d > 0.f;
        float scale = up ? t : 1.f;
        float wv = up ? 1.f : t;
        m = up ? a : m;
        denom = fmaf(denom, scale, wv);
        if (lane < 10) {
            float4 v = *(const float4*)&g_h2[s * 40 + lane * 4];
            acc.x = fmaf(wv, v.x, acc.x * scale);
            acc.y = fmaf(wv, v.y, acc.y * scale);
            acc.z = fmaf(wv, v.z, acc.z * scale);
            acc.w = fmaf(wv, v.w, acc.w * scale);
        }
    }
    float inv = 1.f / (denom + 1e-16f);
    if (lane < 10) {
        float4 b = *(const float4*)&bias[lane * 4];
        *(float4*)&out[node * 40 + lane * 4] =
            make_float4(fmaf(acc.x, inv, b.x), fmaf(acc.y, inv, b.y),
                        fmaf(acc.z, inv, b.z), fmaf(acc.w, inv, b.w));
    }
}

// ---------------- launch ----------------------------------------------------
extern "C" void kernel_launch(void* const* d_in, const int* in_sizes, int n_in,
                              void* d_out, int out_size) {
    const float* x        = (const float*)d_in[0];
    const int*   ei       = (const int*)d_in[1];
    const float* W1       = (const float*)d_in[2];
    const float* att_src1 = (const float*)d_in[3];
    const float* att_dst1 = (const float*)d_in[4];
    const float* bias1    = (const float*)d_in[5];
    const float* W2       = (const float*)d_in[6];
    const float* att_src2 = (const float*)d_in[7];
    const float* att_dst2 = (const float*)d_in[8];
    const float* bias2    = (const float*)d_in[9];
    float* out = (float*)d_out;

    int N = in_sizes[0] / 128;
    int E = in_sizes[1] / 2;
    const int* src = ei;
    const int* dst = ei + E;

    float *h1p, *out1p, *h2p;
    int *cntp, *offp, *curp;
    cudaGetSymbolAddress((void**)&h1p, g_h1);
    cudaGetSymbolAddress((void**)&out1p, g_out1);
    cudaGetSymbolAddress((void**)&h2p, g_h2);
    cudaGetSymbolAddress((void**)&cntp, g_cnt);
    cudaGetSymbolAddress((void**)&offp, g_off);
    cudaGetSymbolAddress((void**)&curp, g_cursor);

    int smem1 = (17408 + 64 * 132 + 256) * 4;            // 104448 B
    int smem2 = (128 * 44 + 128 * 132 + 80) * 4;         // 90432 B
    static bool attr_set = false;
    if (!attr_set) {
        cudaFuncSetAttribute(gemm1_tf32_kernel,
                             cudaFuncAttributeMaxDynamicSharedMemorySize, smem1);
        cudaFuncSetAttribute(gemm2_tf32_kernel,
                             cudaFuncAttributeMaxDynamicSharedMemorySize, smem2);
        attr_set = true;
    }

    int eb = (E + 255) / 256;
    int eb4 = ((E + 3) / 4 + 255) / 256;
    int wb = (N + 7) / 8;
    int gb1 = (N + 63) / 64;
    int gb2 = (N + 127) / 128;

    prep_w1_kernel<<<64, 256>>>(W1);

    // CSR build (shared by both layers)
    cudaMemsetAsync(cntp, 0, (size_t)N * sizeof(int));
    hist_kernel<<<eb4, 256>>>(dst, E);
    scan_kernel<<<1, 1024>>>(N);
    cudaMemcpyAsync(curp, offp, (size_t)N * sizeof(int), cudaMemcpyDeviceToDevice);
    scatter_kernel<<<eb, 256>>>(src, dst, E);

    // layer 1
    gemm1_tf32_kernel<<<gb1, 256, smem1>>>(x, att_src1, att_dst1, h1p, N);
    agg1_kernel<<<wb, 256>>>(bias1, N);

    // layer 2
    gemm2_tf32_kernel<<<gb2, 256, smem2>>>(out1p, W2, att_src2, att_dst2, h2p, N);
    agg2_kernel<<<wb, 256>>>(bias2, out, N);
}

// round 6
// speedup vs baseline: 1.4376x; 1.4376x over previous
#include <cuda_runtime.h>
#include <cstdint>

#define NEG_SLOPE 0.2f

static const int NMAX = 50000;
static const int EMAX = 800000;

// ---------------- scratch ---------------------------------------------------
__device__ __align__(16) float g_h1[NMAX * 128];
__device__ __align__(16) float g_out1[NMAX * 128];
__device__ __align__(16) float g_h2[NMAX * 40];
__device__ __align__(16) float g_asrc1[NMAX * 8];
__device__ __align__(16) float g_adst1[NMAX * 8];
__device__ __align__(16) float g_asrc2[NMAX];
__device__ __align__(16) float g_adst2[NMAX];
__device__ __align__(16) uint32_t g_w1p[2 * 16 * 8 * 68];   // permuted tf32 W1
__device__ int g_cnt[NMAX];
__device__ int g_off[NMAX + 1];
__device__ int g_cursor[NMAX];
__device__ int g_csr[EMAX];

__device__ __forceinline__ float lrelu(float v) { return v > 0.f ? v : NEG_SLOPE * v; }
__device__ __forceinline__ uint32_t f2tf32(float f) {
    uint32_t u;
    asm("cvt.rna.tf32.f32 %0, %1;" : "=r"(u) : "f"(f));
    return u;
}

// ---------------- W1 prep: tf32 + fragment-order permute --------------------
__global__ void prep_w1_kernel(const float* __restrict__ W) {
    int i = blockIdx.x * 256 + threadIdx.x;
    if (i >= 128 * 128) return;
    int k = i >> 7, n = i & 127;
    int half = n >> 6, kt = k >> 3, kq = k & 7;
    int c = n & 63;
    int slot = (c & 7) * 8 + (c >> 3);   // transpose: slot(g,nt) holds col nt*8+g
    g_w1p[((half * 16 + kt) * 8 + kq) * 68 + slot] = f2tf32(W[k * 128 + n]);
}

// ---------------- CSR build -------------------------------------------------
__global__ void hist_kernel(const int* __restrict__ dst, int E) {
    int e4 = blockIdx.x * blockDim.x + threadIdx.x;
    if (e4 * 4 + 3 < E) {
        int4 d = ((const int4*)dst)[e4];
        atomicAdd(&g_cnt[d.x], 1);
        atomicAdd(&g_cnt[d.y], 1);
        atomicAdd(&g_cnt[d.z], 1);
        atomicAdd(&g_cnt[d.w], 1);
    } else {
        for (int e = e4 * 4; e < E; e++) atomicAdd(&g_cnt[dst[e]], 1);
    }
}

__global__ void scan_kernel(int n) {
    __shared__ int wsum[32];
    int tid = threadIdx.x;
    int lane = tid & 31, w = tid >> 5;
    int chunk = (n + 1023) >> 10;
    int beg = tid * chunk;
    int end = min(beg + chunk, n);
    int s = 0;
    for (int i = beg; i < end; i++) s += g_cnt[i];
    int v = s;
#pragma unroll
    for (int o = 1; o < 32; o <<= 1) {
        int t = __shfl_up_sync(0xffffffffu, v, o);
        if (lane >= o) v += t;
    }
    if (lane == 31) wsum[w] = v;
    __syncthreads();
    if (w == 0) {
        int x = wsum[lane];
#pragma unroll
        for (int o = 1; o < 32; o <<= 1) {
            int t = __shfl_up_sync(0xffffffffu, x, o);
            if (lane >= o) x += t;
        }
        wsum[lane] = x;
    }
    __syncthreads();
    int run = v - s + (w ? wsum[w - 1] : 0);
    for (int i = beg; i < end; i++) {
        int c = g_cnt[i];
        g_off[i] = run;
        run += c;
    }
    if (tid == 1023) g_off[n] = run;
}

__global__ void scatter_kernel(const int* __restrict__ src,
                               const int* __restrict__ dst, int E) {
    int e = blockIdx.x * blockDim.x + threadIdx.x;
    if (e < E) {
        int d = dst[e];
        int pos = atomicAdd(&g_cursor[d], 1);
        g_csr[pos] = src[e];
    }
}

// ---------------- layer1 GEMM: TF32 mma + fused attention logits ------------
__global__ __launch_bounds__(256) void gemm1_tf32_kernel(
    const float* __restrict__ X,
    const float* __restrict__ att_src, const float* __restrict__ att_dst,
    float* __restrict__ Y, int N) {
    const int XS = 132;
    extern __shared__ float smf[];
    uint32_t* ws = (uint32_t*)smf;                  // 17408 u32 (permuted tf32 W)
    uint32_t* xs = (uint32_t*)(smf + 17408);        // 64 x XS
    float* satt = smf + 17408 + 64 * XS;            // 256 floats
    int tid = threadIdx.x;

    for (int i = tid; i < 17408 / 4; i += 256)
        ((uint4*)ws)[i] = ((const uint4*)g_w1p)[i];
    satt[tid] = (tid < 128) ? att_src[tid] : att_dst[tid - 128];

    int row0 = blockIdx.x * 64;
    for (int i = tid; i < 64 * 32; i += 256) {
        int r = i >> 5, k4 = (i & 31) * 4;
        int row = row0 + r;
        float4 v = (row < N) ? *(const float4*)&X[row * 128 + k4]
                             : make_float4(0.f, 0.f, 0.f, 0.f);
        uint32_t* p = &xs[r * XS + k4];
        p[0] = f2tf32(v.x); p[1] = f2tf32(v.y); p[2] = f2tf32(v.z); p[3] = f2tf32(v.w);
    }
    __syncthreads();

    int lane = tid & 31, wid = tid >> 5;
    int wm = (wid >> 1) * 16;
    int wn = (wid & 1) * 64;
    int q = lane & 3, g = lane >> 2;
    int half = wn >> 6;

    float c[8][4];
#pragma unroll
    for (int nt = 0; nt < 8; nt++)
#pragma unroll
        for (int j = 0; j < 4; j++) c[nt][j] = 0.f;

#pragma unroll
    for (int kt = 0; kt < 16; kt++) {
        int k0 = kt * 8;
        int ar = wm + g;
        uint32_t a0 = xs[ar * XS + k0 + q];
        uint32_t a1 = xs[(ar + 8) * XS + k0 + q];
        uint32_t a2 = xs[ar * XS + k0 + q + 4];
        uint32_t a3 = xs[(ar + 8) * XS + k0 + q + 4];
        const uint32_t* wp = ws + (half * 16 + kt) * 8 * 68;
        uint4 b0lo = *(const uint4*)&wp[q * 68 + g * 8];
        uint4 b0hi = *(const uint4*)&wp[q * 68 + g * 8 + 4];
        uint4 b1lo = *(const uint4*)&wp[(q + 4) * 68 + g * 8];
        uint4 b1hi = *(const uint4*)&wp[(q + 4) * 68 + g * 8 + 4];
        uint32_t b0v[8] = {b0lo.x, b0lo.y, b0lo.z, b0lo.w, b0hi.x, b0hi.y, b0hi.z, b0hi.w};
        uint32_t b1v[8] = {b1lo.x, b1lo.y, b1lo.z, b1lo.w, b1hi.x, b1hi.y, b1hi.z, b1hi.w};
#pragma unroll
        for (int nt = 0; nt < 8; nt++) {
            asm volatile(
                "mma.sync.aligned.m16n8k8.row.col.f32.tf32.tf32.f32 "
                "{%0,%1,%2,%3},{%4,%5,%6,%7},{%8,%9},{%0,%1,%2,%3};"
                : "+f"(c[nt][0]), "+f"(c[nt][1]), "+f"(c[nt][2]), "+f"(c[nt][3])
                : "r"(a0), "r"(a1), "r"(a2), "r"(a3), "r"(b0v[nt]), "r"(b1v[nt]));
        }
    }

    int r_lo = row0 + wm + g;
    int r_hi = r_lo + 8;
    float ps_lo[4] = {0, 0, 0, 0}, pd_lo[4] = {0, 0, 0, 0};
    float ps_hi[4] = {0, 0, 0, 0}, pd_hi[4] = {0, 0, 0, 0};
#pragma unroll
    for (int nt = 0; nt < 8; nt++) {
        int col = wn + nt * 8 + 2 * q;
        float as0 = satt[col], as1 = satt[col + 1];
        float ad0 = satt[128 + col], ad1 = satt[128 + col + 1];
        int lh = nt >> 1;
        ps_lo[lh] += c[nt][0] * as0 + c[nt][1] * as1;
        pd_lo[lh] += c[nt][0] * ad0 + c[nt][1] * ad1;
        ps_hi[lh] += c[nt][2] * as0 + c[nt][3] * as1;
        pd_hi[lh] += c[nt][2] * ad0 + c[nt][3] * ad1;
        if (r_lo < N) *(float2*)&Y[r_lo * 128 + col] = make_float2(c[nt][0], c[nt][1]);
        if (r_hi < N) *(float2*)&Y[r_hi * 128 + col] = make_float2(c[nt][2], c[nt][3]);
    }
#pragma unroll
    for (int lh = 0; lh < 4; lh++) {
#pragma unroll
        for (int o = 1; o <= 2; o <<= 1) {
            ps_lo[lh] += __shfl_xor_sync(0xffffffffu, ps_lo[lh], o);
            pd_lo[lh] += __shfl_xor_sync(0xffffffffu, pd_lo[lh], o);
            ps_hi[lh] += __shfl_xor_sync(0xffffffffu, ps_hi[lh], o);
            pd_hi[lh] += __shfl_xor_sync(0xffffffffu, pd_hi[lh], o);
        }
    }
    if (q == 0) {
        int hb = wn >> 4;
#pragma unroll
        for (int lh = 0; lh < 4; lh++) {
            int h = hb + lh;
            if (r_lo < N) { g_asrc1[r_lo * 8 + h] = ps_lo[lh]; g_adst1[r_lo * 8 + h] = pd_lo[lh]; }
            if (r_hi < N) { g_asrc1[r_hi * 8 + h] = ps_hi[lh]; g_adst1[r_hi * 8 + h] = pd_hi[lh]; }
        }
    }
}

// ---------------- layer2 GEMM (TF32) + fused att2 logits --------------------
__global__ __launch_bounds__(256) void gemm2_tf32_kernel(
    const float* __restrict__ X, const float* __restrict__ W,
    const float* __restrict__ att_src, const float* __restrict__ att_dst,
    float* __restrict__ Y, int N) {
    const int WS2 = 44, XS = 132;
    extern __shared__ float smf[];
    uint32_t* ws = (uint32_t*)smf;                   // 128 x WS2
    uint32_t* xs = (uint32_t*)(smf + 128 * WS2);     // 128 x XS
    float* satt = smf + 128 * WS2 + 128 * XS;        // 80 floats
    int tid = threadIdx.x;

    for (int i = tid; i < 128 * 40; i += 256) {
        int k = i / 40, n = i % 40;
        ws[k * WS2 + n] = f2tf32(W[i]);
    }
    if (tid < 40) satt[tid] = att_src[tid];
    else if (tid < 80) satt[tid] = att_dst[tid - 40];

    int row0 = blockIdx.x * 128;
    for (int i = tid; i < 128 * 32; i += 256) {
        int r = i >> 5, k4 = (i & 31) * 4;
        int row = row0 + r;
        float4 v = (row < N) ? *(const float4*)&X[row * 128 + k4]
                             : make_float4(0.f, 0.f, 0.f, 0.f);
        uint32_t* p = &xs[r * XS + k4];
        p[0] = f2tf32(v.x); p[1] = f2tf32(v.y); p[2] = f2tf32(v.z); p[3] = f2tf32(v.w);
    }
    __syncthreads();

    int lane = tid & 31, wid = tid >> 5;
    int wm = wid * 16;
    int q = lane & 3, g = lane >> 2;

    float c[5][4];
#pragma unroll
    for (int nt = 0; nt < 5; nt++)
#pragma unroll
        for (int j = 0; j < 4; j++) c[nt][j] = 0.f;

#pragma unroll
    for (int kt = 0; kt < 16; kt++) {
        int k0 = kt * 8;
        int ar = wm + g;
        uint32_t a0 = xs[ar * XS + k0 + q];
        uint32_t a1 = xs[(ar + 8) * XS + k0 + q];
        uint32_t a2 = xs[ar * XS + k0 + q + 4];
        uint32_t a3 = xs[(ar + 8) * XS + k0 + q + 4];
#pragma unroll
        for (int nt = 0; nt < 5; nt++) {
            uint32_t b0 = ws[(k0 + q) * WS2 + nt * 8 + g];
            uint32_t b1 = ws[(k0 + q + 4) * WS2 + nt * 8 + g];
            asm volatile(
                "mma.sync.aligned.m16n8k8.row.col.f32.tf32.tf32.f32 "
                "{%0,%1,%2,%3},{%4,%5,%6,%7},{%8,%9},{%0,%1,%2,%3};"
                : "+f"(c[nt][0]), "+f"(c[nt][1]), "+f"(c[nt][2]), "+f"(c[nt][3])
                : "r"(a0), "r"(a1), "r"(a2), "r"(a3), "r"(b0), "r"(b1));
        }
    }

    int r_lo = row0 + wm + g;
    int r_hi = r_lo + 8;
    float ps_lo = 0.f, pd_lo = 0.f, ps_hi = 0.f, pd_hi = 0.f;
#pragma unroll
    for (int nt = 0; nt < 5; nt++) {
        int col = nt * 8 + 2 * q;
        float as0 = satt[col], as1 = satt[col + 1];
        float ad0 = satt[40 + col], ad1 = satt[40 + col + 1];
        ps_lo += c[nt][0] * as0 + c[nt][1] * as1;
        pd_lo += c[nt][0] * ad0 + c[nt][1] * ad1;
        ps_hi += c[nt][2] * as0 + c[nt][3] * as1;
        pd_hi += c[nt][2] * ad0 + c[nt][3] * ad1;
        if (r_lo < N) *(float2*)&Y[r_lo * 40 + col] = make_float2(c[nt][0], c[nt][1]);
        if (r_hi < N) *(float2*)&Y[r_hi * 40 + col] = make_float2(c[nt][2], c[nt][3]);
    }
#pragma unroll
    for (int o = 1; o <= 2; o <<= 1) {
        ps_lo += __shfl_xor_sync(0xffffffffu, ps_lo, o);
        pd_lo += __shfl_xor_sync(0xffffffffu, pd_lo, o);
        ps_hi += __shfl_xor_sync(0xffffffffu, ps_hi, o);
        pd_hi += __shfl_xor_sync(0xffffffffu, pd_hi, o);
    }
    if (q == 0) {
        if (r_lo < N) { g_asrc2[r_lo] = ps_lo; g_adst2[r_lo] = pd_lo; }
        if (r_hi < N) { g_asrc2[r_hi] = ps_hi; g_adst2[r_hi] = pd_hi; }
    }
}

// ---------------- aggregation: two-pass (max, then exp/accumulate) ----------
__global__ void agg1_kernel(const float* __restrict__ bias, int N) {
    int node = (blockIdx.x * blockDim.x + threadIdx.x) >> 5;
    if (node >= N) return;
    int lane = threadIdx.x & 31;
    int h = lane >> 2;
    int beg = g_off[node], end = g_off[node + 1];

    float adst = g_adst1[node * 8 + h];
    float aself = lrelu(g_asrc1[node * 8 + h] + adst);
    float m = aself;
    for (int e = beg; e < end; e++) {
        int s = g_csr[e];
        m = fmaxf(m, lrelu(g_asrc1[s * 8 + h] + adst));
    }
    float w = __expf(aself - m);
    float denom = w;
    float4 hv = *(const float4*)&g_h1[node * 128 + lane * 4];
    float4 acc = make_float4(w * hv.x, w * hv.y, w * hv.z, w * hv.w);
    for (int e = beg; e < end; e++) {
        int s = g_csr[e];
        float wv = __expf(lrelu(g_asrc1[s * 8 + h] + adst) - m);
        denom += wv;
        float4 v = *(const float4*)&g_h1[s * 128 + lane * 4];
        acc.x = fmaf(wv, v.x, acc.x);
        acc.y = fmaf(wv, v.y, acc.y);
        acc.z = fmaf(wv, v.z, acc.z);
        acc.w = fmaf(wv, v.w, acc.w);
    }
    float inv = 1.f / (denom + 1e-16f);
    float4 b = *(const float4*)&bias[lane * 4];
    *(float4*)&g_out1[node * 128 + lane * 4] =
        make_float4(fmaf(acc.x, inv, b.x), fmaf(acc.y, inv, b.y),
                    fmaf(acc.z, inv, b.z), fmaf(acc.w, inv, b.w));
}

__global__ void agg2_kernel(const float* __restrict__ bias, float* __restrict__ out, int N) {
    int node = (blockIdx.x * blockDim.x + threadIdx.x) >> 5;
    if (node >= N) return;
    int lane = threadIdx.x & 31;
    int beg = g_off[node], end = g_off[node + 1];

    float adst = g_adst2[node];
    float aself = lrelu(g_asrc2[node] + adst);
    float m = aself;
    for (int e = beg; e < end; e++) {
        int s = g_csr[e];
        m = fmaxf(m, lrelu(g_asrc2[s] + adst));
    }
    float w = __expf(aself - m);
    float denom = w;
    float4 acc = make_float4(0.f, 0.f, 0.f, 0.f);
    if (lane < 10) {
        float4 hv = *(const float4*)&g_h2[node * 40 + lane * 4];
        acc = make_float4(w * hv.x, w * hv.y, w * hv.z, w * hv.w);
    }
    for (int e = beg; e < end; e++) {
        int s = g_csr[e];
        float wv = __expf(lrelu(g_asrc2[s] + adst) - m);
        denom += wv;
        if (lane < 10) {
            float4 v = *(const float4*)&g_h2[s * 40 + lane * 4];
            acc.x = fmaf(wv, v.x, acc.x);
            acc.y = fmaf(wv, v.y, acc.y);
            acc.z = fmaf(wv, v.z, acc.z);
            acc.w = fmaf(wv, v.w, acc.w);
        }
    }
    float inv = 1.f / (denom + 1e-16f);
    if (lane < 10) {
        float4 b = *(const float4*)&bias[lane * 4];
        *(float4*)&out[node * 40 + lane * 4] =
            make_float4(fmaf(acc.x, inv, b.x), fmaf(acc.y, inv, b.y),
                        fmaf(acc.z, inv, b.z), fmaf(acc.w, inv, b.w));
    }
}

// ---------------- launch ----------------------------------------------------
extern "C" void kernel_launch(void* const* d_in, const int* in_sizes, int n_in,
                              void* d_out, int out_size) {
    const float* x        = (const float*)d_in[0];
    const int*   ei       = (const int*)d_in[1];
    const float* W1       = (const float*)d_in[2];
    const float* att_src1 = (const float*)d_in[3];
    const float* att_dst1 = (const float*)d_in[4];
    const float* bias1    = (const float*)d_in[5];
    const float* W2       = (const float*)d_in[6];
    const float* att_src2 = (const float*)d_in[7];
    const float* att_dst2 = (const float*)d_in[8];
    const float* bias2    = (const float*)d_in[9];
    float* out = (float*)d_out;

    int N = in_sizes[0] / 128;
    int E = in_sizes[1] / 2;
    const int* src = ei;
    const int* dst = ei + E;

    float *h1p, *out1p, *h2p;
    int *cntp, *offp, *curp;
    cudaGetSymbolAddress((void**)&h1p, g_h1);
    cudaGetSymbolAddress((void**)&out1p, g_out1);
    cudaGetSymbolAddress((void**)&h2p, g_h2);
    cudaGetSymbolAddress((void**)&cntp, g_cnt);
    cudaGetSymbolAddress((void**)&offp, g_off);
    cudaGetSymbolAddress((void**)&curp, g_cursor);

    int smem1 = (17408 + 64 * 132 + 256) * 4;            // 104448 B
    int smem2 = (128 * 44 + 128 * 132 + 80) * 4;         // 90432 B
    static bool attr_set = false;
    if (!attr_set) {
        cudaFuncSetAttribute(gemm1_tf32_kernel,
                             cudaFuncAttributeMaxDynamicSharedMemorySize, smem1);
        cudaFuncSetAttribute(gemm2_tf32_kernel,
                             cudaFuncAttributeMaxDynamicSharedMemorySize, smem2);
        attr_set = true;
    }

    int eb = (E + 255) / 256;
    int eb4 = ((E + 3) / 4 + 255) / 256;
    int wb = (N + 7) / 8;
    int gb1 = (N + 63) / 64;
    int gb2 = (N + 127) / 128;

    prep_w1_kernel<<<64, 256>>>(W1);

    // CSR build (shared by both layers)
    cudaMemsetAsync(cntp, 0, (size_t)N * sizeof(int));
    hist_kernel<<<eb4, 256>>>(dst, E);
    scan_kernel<<<1, 1024>>>(N);
    cudaMemcpyAsync(curp, offp, (size_t)N * sizeof(int), cudaMemcpyDeviceToDevice);
    scatter_kernel<<<eb, 256>>>(src, dst, E);

    // layer 1
    gemm1_tf32_kernel<<<gb1, 256, smem1>>>(x, att_src1, att_dst1, h1p, N);
    agg1_kernel<<<wb, 256>>>(bias1, N);

    // layer 2
    gemm2_tf32_kernel<<<gb2, 256, smem2>>>(out1p, W2, att_src2, att_dst2, h2p, N);
    agg2_kernel<<<wb, 256>>>(bias2, out, N);
}

// round 8
// speedup vs baseline: 1.6056x; 1.1169x over previous
#include <cuda_runtime.h>
#include <cuda_fp16.h>
#include <cstdint>

#define NEG_SLOPE 0.2f

static const int NMAX = 50000;
static const int EMAX = 800000;

// ---------------- scratch ---------------------------------------------------
__device__ __align__(16) __half g_h1h[NMAX * 128];   // layer1 features (fp16)
__device__ __align__(16) float g_out1[NMAX * 128];
__device__ __align__(16) float g_h2[NMAX * 40];
__device__ __align__(16) float g_asrc1[NMAX * 8];
__device__ __align__(16) float g_adst1[NMAX * 8];
__device__ __align__(16) float g_asrc2[NMAX];
__device__ __align__(16) float g_adst2[NMAX];
__device__ __align__(16) uint32_t g_w1p[2 * 16 * 8 * 68];   // permuted tf32 W1
__device__ int g_cnt[NMAX];
__device__ int g_off[NMAX + 1];
__device__ int g_cursor[NMAX];
__device__ int g_csr[EMAX];

__device__ __forceinline__ float lrelu(float v) { return v > 0.f ? v : NEG_SLOPE * v; }
__device__ __forceinline__ uint32_t f2tf32(float f) {
    uint32_t u;
    asm("cvt.rna.tf32.f32 %0, %1;" : "=r"(u) : "f"(f));
    return u;
}

// ---------------- W1 prep: tf32 + fragment-order permute --------------------
__global__ void prep_w1_kernel(const float* __restrict__ W) {
    int i = blockIdx.x * 256 + threadIdx.x;
    if (i >= 128 * 128) return;
    int k = i >> 7, n = i & 127;
    int half_ = n >> 6, kt = k >> 3, kq = k & 7;
    int c = n & 63;
    int slot = (c & 7) * 8 + (c >> 3);
    g_w1p[((half_ * 16 + kt) * 8 + kq) * 68 + slot] = f2tf32(W[k * 128 + n]);
}

// ---------------- CSR build -------------------------------------------------
__global__ void hist_kernel(const int* __restrict__ dst, int E) {
    int e4 = blockIdx.x * blockDim.x + threadIdx.x;
    if (e4 * 4 + 3 < E) {
        int4 d = ((const int4*)dst)[e4];
        atomicAdd(&g_cnt[d.x], 1);
        atomicAdd(&g_cnt[d.y], 1);
        atomicAdd(&g_cnt[d.z], 1);
        atomicAdd(&g_cnt[d.w], 1);
    } else {
        for (int e = e4 * 4; e < E; e++) atomicAdd(&g_cnt[dst[e]], 1);
    }
}

__global__ void scan_kernel(int n) {
    __shared__ int wsum[32];
    int tid = threadIdx.x;
    int lane = tid & 31, w = tid >> 5;
    int chunk = (n + 1023) >> 10;
    int beg = tid * chunk;
    int end = min(beg + chunk, n);
    int s = 0;
    for (int i = beg; i < end; i++) s += g_cnt[i];
    int v = s;
#pragma unroll
    for (int o = 1; o < 32; o <<= 1) {
        int t = __shfl_up_sync(0xffffffffu, v, o);
        if (lane >= o) v += t;
    }
    if (lane == 31) wsum[w] = v;
    __syncthreads();
    if (w == 0) {
        int x = wsum[lane];
#pragma unroll
        for (int o = 1; o < 32; o <<= 1) {
            int t = __shfl_up_sync(0xffffffffu, x, o);
            if (lane >= o) x += t;
        }
        wsum[lane] = x;
    }
    __syncthreads();
    int run = v - s + (w ? wsum[w - 1] : 0);
    for (int i = beg; i < end; i++) {
        int c = g_cnt[i];
        g_off[i] = run;
        run += c;
    }
    if (tid == 1023) g_off[n] = run;
}

__global__ void scatter_kernel(const int* __restrict__ src,
                               const int* __restrict__ dst, int E) {
    int e = blockIdx.x * blockDim.x + threadIdx.x;
    if (e < E) {
        int d = dst[e];
        int pos = atomicAdd(&g_cursor[d], 1);
        g_csr[pos] = src[e];
    }
}

// ---------------- layer1 GEMM: TF32 mma + fused att logits, fp16 output -----
__global__ __launch_bounds__(256) void gemm1_tf32_kernel(
    const float* __restrict__ X,
    const float* __restrict__ att_src, const float* __restrict__ att_dst,
    int N) {
    const int XS = 132;
    extern __shared__ float smf[];
    uint32_t* ws = (uint32_t*)smf;                  // 17408 u32 (permuted tf32 W)
    uint32_t* xs = (uint32_t*)(smf + 17408);        // 64 x XS
    float* satt = smf + 17408 + 64 * XS;            // 256 floats
    int tid = threadIdx.x;

    for (int i = tid; i < 17408 / 4; i += 256)
        ((uint4*)ws)[i] = ((const uint4*)g_w1p)[i];
    satt[tid] = (tid < 128) ? att_src[tid] : att_dst[tid - 128];

    int row0 = blockIdx.x * 64;
    for (int i = tid; i < 64 * 32; i += 256) {
        int r = i >> 5, k4 = (i & 31) * 4;
        int row = row0 + r;
        float4 v = (row < N) ? *(const float4*)&X[row * 128 + k4]
                             : make_float4(0.f, 0.f, 0.f, 0.f);
        uint32_t* p = &xs[r * XS + k4];
        p[0] = f2tf32(v.x); p[1] = f2tf32(v.y); p[2] = f2tf32(v.z); p[3] = f2tf32(v.w);
    }
    __syncthreads();

    int lane = tid & 31, wid = tid >> 5;
    int wm = (wid >> 1) * 16;
    int wn = (wid & 1) * 64;
    int q = lane & 3, g = lane >> 2;
    int half_ = wn >> 6;

    float c[8][4];
#pragma unroll
    for (int nt = 0; nt < 8; nt++)
#pragma unroll
        for (int j = 0; j < 4; j++) c[nt][j] = 0.f;

#pragma unroll
    for (int kt = 0; kt < 16; kt++) {
        int k0 = kt * 8;
        int ar = wm + g;
        uint32_t a0 = xs[ar * XS + k0 + q];
        uint32_t a1 = xs[(ar + 8) * XS + k0 + q];
        uint32_t a2 = xs[ar * XS + k0 + q + 4];
        uint32_t a3 = xs[(ar + 8) * XS + k0 + q + 4];
        const uint32_t* wp = ws + (half_ * 16 + kt) * 8 * 68;
        uint4 b0lo = *(const uint4*)&wp[q * 68 + g * 8];
        uint4 b0hi = *(const uint4*)&wp[q * 68 + g * 8 + 4];
        uint4 b1lo = *(const uint4*)&wp[(q + 4) * 68 + g * 8];
        uint4 b1hi = *(const uint4*)&wp[(q + 4) * 68 + g * 8 + 4];
        uint32_t b0v[8] = {b0lo.x, b0lo.y, b0lo.z, b0lo.w, b0hi.x, b0hi.y, b0hi.z, b0hi.w};
        uint32_t b1v[8] = {b1lo.x, b1lo.y, b1lo.z, b1lo.w, b1hi.x, b1hi.y, b1hi.z, b1hi.w};
#pragma unroll
        for (int nt = 0; nt < 8; nt++) {
            asm volatile(
                "mma.sync.aligned.m16n8k8.row.col.f32.tf32.tf32.f32 "
                "{%0,%1,%2,%3},{%4,%5,%6,%7},{%8,%9},{%0,%1,%2,%3};"
                : "+f"(c[nt][0]), "+f"(c[nt][1]), "+f"(c[nt][2]), "+f"(c[nt][3])
                : "r"(a0), "r"(a1), "r"(a2), "r"(a3), "r"(b0v[nt]), "r"(b1v[nt]));
        }
    }

    int r_lo = row0 + wm + g;
    int r_hi = r_lo + 8;
    float ps_lo[4] = {0, 0, 0, 0}, pd_lo[4] = {0, 0, 0, 0};
    float ps_hi[4] = {0, 0, 0, 0}, pd_hi[4] = {0, 0, 0, 0};
#pragma unroll
    for (int nt = 0; nt < 8; nt++) {
        int col = wn + nt * 8 + 2 * q;
        float as0 = satt[col], as1 = satt[col + 1];
        float ad0 = satt[128 + col], ad1 = satt[128 + col + 1];
        int lh = nt >> 1;
        ps_lo[lh] += c[nt][0] * as0 + c[nt][1] * as1;
        pd_lo[lh] += c[nt][0] * ad0 + c[nt][1] * ad1;
        ps_hi[lh] += c[nt][2] * as0 + c[nt][3] * as1;
        pd_hi[lh] += c[nt][2] * ad0 + c[nt][3] * ad1;
        if (r_lo < N)
            *(__half2*)&g_h1h[r_lo * 128 + col] = __floats2half2_rn(c[nt][0], c[nt][1]);
        if (r_hi < N)
            *(__half2*)&g_h1h[r_hi * 128 + col] = __floats2half2_rn(c[nt][2], c[nt][3]);
    }
#pragma unroll
    for (int lh = 0; lh < 4; lh++) {
#pragma unroll
        for (int o = 1; o <= 2; o <<= 1) {
            ps_lo[lh] += __shfl_xor_sync(0xffffffffu, ps_lo[lh], o);
            pd_lo[lh] += __shfl_xor_sync(0xffffffffu, pd_lo[lh], o);
            ps_hi[lh] += __shfl_xor_sync(0xffffffffu, ps_hi[lh], o);
            pd_hi[lh] += __shfl_xor_sync(0xffffffffu, pd_hi[lh], o);
        }
    }
    if (q == 0) {
        int hb = wn >> 4;
#pragma unroll
        for (int lh = 0; lh < 4; lh++) {
            int h = hb + lh;
            if (r_lo < N) { g_asrc1[r_lo * 8 + h] = ps_lo[lh]; g_adst1[r_lo * 8 + h] = pd_lo[lh]; }
            if (r_hi < N) { g_asrc1[r_hi * 8 + h] = ps_hi[lh]; g_adst1[r_hi * 8 + h] = pd_hi[lh]; }
        }
    }
}

// ---------------- layer2 GEMM (TF32) + fused att2 logits --------------------
__global__ __launch_bounds__(256) void gemm2_tf32_kernel(
    const float* __restrict__ X, const float* __restrict__ W,
    const float* __restrict__ att_src, const float* __restrict__ att_dst,
    float* __restrict__ Y, int N) {
    const int WS2 = 44, XS = 132;
    extern __shared__ float smf[];
    uint32_t* ws = (uint32_t*)smf;                   // 128 x WS2
    uint32_t* xs = (uint32_t*)(smf + 128 * WS2);     // 128 x XS
    float* satt = smf + 128 * WS2 + 128 * XS;        // 80 floats
    int tid = threadIdx.x;

    for (int i = tid; i < 128 * 40; i += 256) {
        int k = i / 40, n = i % 40;
        ws[k * WS2 + n] = f2tf32(W[i]);
    }
    if (tid < 40) satt[tid] = att_src[tid];
    else if (tid < 80) satt[tid] = att_dst[tid - 40];

    int row0 = blockIdx.x * 128;
    for (int i = tid; i < 128 * 32; i += 256) {
        int r = i >> 5, k4 = (i & 31) * 4;
        int row = row0 + r;
        float4 v = (row < N) ? *(const float4*)&X[row * 128 + k4]
                             : make_float4(0.f, 0.f, 0.f, 0.f);
        uint32_t* p = &xs[r * XS + k4];
        p[0] = f2tf32(v.x); p[1] = f2tf32(v.y); p[2] = f2tf32(v.z); p[3] = f2tf32(v.w);
    }
    __syncthreads();

    int lane = tid & 31, wid = tid >> 5;
    int wm = wid * 16;
    int q = lane & 3, g = lane >> 2;

    float c[5][4];
#pragma unroll
    for (int nt = 0; nt < 5; nt++)
#pragma unroll
        for (int j = 0; j < 4; j++) c[nt][j] = 0.f;

#pragma unroll
    for (int kt = 0; kt < 16; kt++) {
        int k0 = kt * 8;
        int ar = wm + g;
        uint32_t a0 = xs[ar * XS + k0 + q];
        uint32_t a1 = xs[(ar + 8) * XS + k0 + q];
        uint32_t a2 = xs[ar * XS + k0 + q + 4];
        uint32_t a3 = xs[(ar + 8) * XS + k0 + q + 4];
#pragma unroll
        for (int nt = 0; nt < 5; nt++) {
            uint32_t b0 = ws[(k0 + q) * WS2 + nt * 8 + g];
            uint32_t b1 = ws[(k0 + q + 4) * WS2 + nt * 8 + g];
            asm volatile(
                "mma.sync.aligned.m16n8k8.row.col.f32.tf32.tf32.f32 "
                "{%0,%1,%2,%3},{%4,%5,%6,%7},{%8,%9},{%0,%1,%2,%3};"
                : "+f"(c[nt][0]), "+f"(c[nt][1]), "+f"(c[nt][2]), "+f"(c[nt][3])
                : "r"(a0), "r"(a1), "r"(a2), "r"(a3), "r"(b0), "r"(b1));
        }
    }

    int r_lo = row0 + wm + g;
    int r_hi = r_lo + 8;
    float ps_lo = 0.f, pd_lo = 0.f, ps_hi = 0.f, pd_hi = 0.f;
#pragma unroll
    for (int nt = 0; nt < 5; nt++) {
        int col = nt * 8 + 2 * q;
        float as0 = satt[col], as1 = satt[col + 1];
        float ad0 = satt[40 + col], ad1 = satt[40 + col + 1];
        ps_lo += c[nt][0] * as0 + c[nt][1] * as1;
        pd_lo += c[nt][0] * ad0 + c[nt][1] * ad1;
        ps_hi += c[nt][2] * as0 + c[nt][3] * as1;
        pd_hi += c[nt][2] * ad0 + c[nt][3] * ad1;
        if (r_lo < N) *(float2*)&Y[r_lo * 40 + col] = make_float2(c[nt][0], c[nt][1]);
        if (r_hi < N) *(float2*)&Y[r_hi * 40 + col] = make_float2(c[nt][2], c[nt][3]);
    }
#pragma unroll
    for (int o = 1; o <= 2; o <<= 1) {
        ps_lo += __shfl_xor_sync(0xffffffffu, ps_lo, o);
        pd_lo += __shfl_xor_sync(0xffffffffu, pd_lo, o);
        ps_hi += __shfl_xor_sync(0xffffffffu, ps_hi, o);
        pd_hi += __shfl_xor_sync(0xffffffffu, pd_hi, o);
    }
    if (q == 0) {
        if (r_lo < N) { g_asrc2[r_lo] = ps_lo; g_adst2[r_lo] = pd_lo; }
        if (r_hi < N) { g_asrc2[r_hi] = ps_hi; g_adst2[r_hi] = pd_hi; }
    }
}

// ---------------- aggregation: single pass, no max (logits bounded) ---------
__global__ void agg1_kernel(const float* __restrict__ bias, int N) {
    int node = (blockIdx.x * blockDim.x + threadIdx.x) >> 5;
    if (node >= N) return;
    int lane = threadIdx.x & 31;
    int h = lane >> 2;
    int beg = g_off[node], end = g_off[node + 1];

    float adst = g_adst1[node * 8 + h];
    float w0 = __expf(lrelu(g_asrc1[node * 8 + h] + adst));   // self-loop
    float denom = w0;
    uint2 raw0 = *(const uint2*)&g_h1h[node * 128 + lane * 4];
    float2 f0a = __half22float2(*(__half2*)&raw0.x);
    float2 f0b = __half22float2(*(__half2*)&raw0.y);
    float4 acc = make_float4(w0 * f0a.x, w0 * f0a.y, w0 * f0b.x, w0 * f0b.y);

#pragma unroll 4
    for (int e = beg; e < end; e++) {
        int s = g_csr[e];
        float wv = __expf(lrelu(g_asrc1[s * 8 + h] + adst));
        uint2 raw = *(const uint2*)&g_h1h[s * 128 + lane * 4];
        float2 fa = __half22float2(*(__half2*)&raw.x);
        float2 fb = __half22float2(*(__half2*)&raw.y);
        denom += wv;
        acc.x = fmaf(wv, fa.x, acc.x);
        acc.y = fmaf(wv, fa.y, acc.y);
        acc.z = fmaf(wv, fb.x, acc.z);
        acc.w = fmaf(wv, fb.y, acc.w);
    }
    float inv = 1.f / (denom + 1e-16f);
    float4 b = *(const float4*)&bias[lane * 4];
    *(float4*)&g_out1[node * 128 + lane * 4] =
        make_float4(fmaf(acc.x, inv, b.x), fmaf(acc.y, inv, b.y),
                    fmaf(acc.z, inv, b.z), fmaf(acc.w, inv, b.w));
}

__global__ void agg2_kernel(const float* __restrict__ bias, float* __restrict__ out, int N) {
    int node = (blockIdx.x * blockDim.x + threadIdx.x) >> 5;
    if (node >= N) return;
    int lane = threadIdx.x & 31;
    int beg = g_off[node], end = g_off[node + 1];

    float adst = g_adst2[node];
    float w0 = __expf(lrelu(g_asrc2[node] + adst));
    float denom = w0;
    float4 acc = make_float4(0.f, 0.f, 0.f, 0.f);
    if (lane < 10) {
        float4 hv = *(const float4*)&g_h2[node * 40 + lane * 4];
        acc = make_float4(w0 * hv.x, w0 * hv.y, w0 * hv.z, w0 * hv.w);
    }

#pragma unroll 4
    for (int e = beg; e < end; e++) {
        int s = g_csr[e];
        float wv = __expf(lrelu(g_asrc2[s] + adst));
        denom += wv;
        if (lane < 10) {
            float4 v = *(const float4*)&g_h2[s * 40 + lane * 4];
            acc.x = fmaf(wv, v.x, acc.x);
            acc.y = fmaf(wv, v.y, acc.y);
            acc.z = fmaf(wv, v.z, acc.z);
            acc.w = fmaf(wv, v.w, acc.w);
        }
    }
    float inv = 1.f / (denom + 1e-16f);
    if (lane < 10) {
        float4 b = *(const float4*)&bias[lane * 4];
        *(float4*)&out[node * 40 + lane * 4] =
            make_float4(fmaf(acc.x, inv, b.x), fmaf(acc.y, inv, b.y),
                        fmaf(acc.z, inv, b.z), fmaf(acc.w, inv, b.w));
    }
}

// ---------------- launch ----------------------------------------------------
extern "C" void kernel_launch(void* const* d_in, const int* in_sizes, int n_in,
                              void* d_out, int out_size) {
    const float* x        = (const float*)d_in[0];
    const int*   ei       = (const int*)d_in[1];
    const float* W1       = (const float*)d_in[2];
    const float* att_src1 = (const float*)d_in[3];
    const float* att_dst1 = (const float*)d_in[4];
    const float* bias1    = (const float*)d_in[5];
    const float* W2       = (const float*)d_in[6];
    const float* att_src2 = (const float*)d_in[7];
    const float* att_dst2 = (const float*)d_in[8];
    const float* bias2    = (const float*)d_in[9];
    float* out = (float*)d_out;

    int N = in_sizes[0] / 128;
    int E = in_sizes[1] / 2;
    const int* src = ei;
    const int* dst = ei + E;

    float *out1p, *h2p;
    int *cntp, *offp, *curp;
    cudaGetSymbolAddress((void**)&out1p, g_out1);
    cudaGetSymbolAddress((void**)&h2p, g_h2);
    cudaGetSymbolAddress((void**)&cntp, g_cnt);
    cudaGetSymbolAddress((void**)&offp, g_off);
    cudaGetSymbolAddress((void**)&curp, g_cursor);

    int smem1 = (17408 + 64 * 132 + 256) * 4;            // 104448 B
    int smem2 = (128 * 44 + 128 * 132 + 80) * 4;         // 90432 B
    static bool attr_set = false;
    if (!attr_set) {
        cudaFuncSetAttribute(gemm1_tf32_kernel,
                             cudaFuncAttributeMaxDynamicSharedMemorySize, smem1);
        cudaFuncSetAttribute(gemm2_tf32_kernel,
                             cudaFuncAttributeMaxDynamicSharedMemorySize, smem2);
        attr_set = true;
    }

    int eb = (E + 255) / 256;
    int eb4 = ((E + 3) / 4 + 255) / 256;
    int wb = (N + 7) / 8;
    int gb1 = (N + 63) / 64;
    int gb2 = (N + 127) / 128;

    prep_w1_kernel<<<64, 256>>>(W1);

    // CSR build (shared by both layers)
    cudaMemsetAsync(cntp, 0, (size_t)N * sizeof(int));
    hist_kernel<<<eb4, 256>>>(dst, E);
    scan_kernel<<<1, 1024>>>(N);
    cudaMemcpyAsync(curp, offp, (size_t)N * sizeof(int), cudaMemcpyDeviceToDevice);
    scatter_kernel<<<eb, 256>>>(src, dst, E);

    // layer 1
    gemm1_tf32_kernel<<<gb1, 256, smem1>>>(x, att_src1, att_dst1, N);
    agg1_kernel<<<wb, 256>>>(bias1, N);

    // layer 2
    gemm2_tf32_kernel<<<gb2, 256, smem2>>>(out1p, W2, att_src2, att_dst2, h2p, N);
    agg2_kernel<<<wb, 256>>>(bias2, out, N);
}

// round 10
// speedup vs baseline: 1.7419x; 1.0849x over previous
#include <cuda_runtime.h>
#include <cuda_fp16.h>
#include <cstdint>

#define NEG_SLOPE 0.2f

static const int NMAX = 50000;
static const int EMAX = 800000;

// ---------------- scratch ---------------------------------------------------
__device__ __align__(16) __half g_h1h[NMAX * 128];   // layer1 features (fp16)
__device__ __align__(16) float g_out1[NMAX * 128];
__device__ __align__(16) float g_h2[NMAX * 40];
__device__ __align__(16) float g_asrc1[NMAX * 8];
__device__ __align__(16) float g_adst1[NMAX * 8];
__device__ __align__(16) float g_asrc2[NMAX];
__device__ __align__(16) float g_adst2[NMAX];
__device__ __align__(16) uint32_t g_w1p[2 * 16 * 8 * 68];   // permuted tf32 W1
__device__ int g_cnt[NMAX];
__device__ int g_off[NMAX + 1];
__device__ int g_cursor[NMAX];
__device__ int g_csr[EMAX];

__device__ __forceinline__ float lrelu(float v) { return v > 0.f ? v : NEG_SLOPE * v; }
__device__ __forceinline__ uint32_t f2tf32(float f) {
    uint32_t u;
    asm("cvt.rna.tf32.f32 %0, %1;" : "=r"(u) : "f"(f));
    return u;
}

// ---------------- W1 prep: tf32 + fragment-order permute --------------------
__global__ void prep_w1_kernel(const float* __restrict__ W) {
    int i = blockIdx.x * 256 + threadIdx.x;
    if (i >= 128 * 128) return;
    int k = i >> 7, n = i & 127;
    int half_ = n >> 6, kt = k >> 3, kq = k & 7;
    int c = n & 63;
    int slot = (c & 7) * 8 + (c >> 3);
    g_w1p[((half_ * 16 + kt) * 8 + kq) * 68 + slot] = f2tf32(W[k * 128 + n]);
}

// ---------------- CSR build -------------------------------------------------
__global__ void hist_kernel(const int* __restrict__ dst, int E) {
    int e4 = blockIdx.x * blockDim.x + threadIdx.x;
    if (e4 * 4 + 3 < E) {
        int4 d = ((const int4*)dst)[e4];
        atomicAdd(&g_cnt[d.x], 1);
        atomicAdd(&g_cnt[d.y], 1);
        atomicAdd(&g_cnt[d.z], 1);
        atomicAdd(&g_cnt[d.w], 1);
    } else {
        for (int e = e4 * 4; e < E; e++) atomicAdd(&g_cnt[dst[e]], 1);
    }
}

// scan writes BOTH g_off and g_cursor (cursor copy folded in)
__global__ void scan_kernel(int n) {
    __shared__ int wsum[32];
    int tid = threadIdx.x;
    int lane = tid & 31, w = tid >> 5;
    int chunk = (n + 1023) >> 10;
    int beg = tid * chunk;
    int end = min(beg + chunk, n);
    int s = 0;
    for (int i = beg; i < end; i++) s += g_cnt[i];
    int v = s;
#pragma unroll
    for (int o = 1; o < 32; o <<= 1) {
        int t = __shfl_up_sync(0xffffffffu, v, o);
        if (lane >= o) v += t;
    }
    if (lane == 31) wsum[w] = v;
    __syncthreads();
    if (w == 0) {
        int x = wsum[lane];
#pragma unroll
        for (int o = 1; o < 32; o <<= 1) {
            int t = __shfl_up_sync(0xffffffffu, x, o);
            if (lane >= o) x += t;
        }
        wsum[lane] = x;
    }
    __syncthreads();
    int run = v - s + (w ? wsum[w - 1] : 0);
    for (int i = beg; i < end; i++) {
        int c = g_cnt[i];
        g_off[i] = run;
        g_cursor[i] = run;
        run += c;
    }
    if (tid == 1023) g_off[n] = run;
}

__global__ void scatter_kernel(const int* __restrict__ src,
                               const int* __restrict__ dst, int E) {
    int e = blockIdx.x * blockDim.x + threadIdx.x;
    if (e < E) {
        int d = dst[e];
        int pos = atomicAdd(&g_cursor[d], 1);
        g_csr[pos] = src[e];
    }
}

// ---------------- layer1 GEMM: TF32 mma + fused att logits, fp16 output -----
__global__ __launch_bounds__(256) void gemm1_tf32_kernel(
    const float* __restrict__ X,
    const float* __restrict__ att_src, const float* __restrict__ att_dst,
    int N) {
    const int XS = 132;
    extern __shared__ float smf[];
    uint32_t* ws = (uint32_t*)smf;                  // 17408 u32 (permuted tf32 W)
    uint32_t* xs = (uint32_t*)(smf + 17408);        // 64 x XS
    float* satt = smf + 17408 + 64 * XS;            // 256 floats
    int tid = threadIdx.x;

    for (int i = tid; i < 17408 / 4; i += 256)
        ((uint4*)ws)[i] = ((const uint4*)g_w1p)[i];
    satt[tid] = (tid < 128) ? att_src[tid] : att_dst[tid - 128];

    int row0 = blockIdx.x * 64;
    for (int i = tid; i < 64 * 32; i += 256) {
        int r = i >> 5, k4 = (i & 31) * 4;
        int row = row0 + r;
        float4 v = (row < N) ? *(const float4*)&X[row * 128 + k4]
                             : make_float4(0.f, 0.f, 0.f, 0.f);
        uint32_t* p = &xs[r * XS + k4];
        p[0] = f2tf32(v.x); p[1] = f2tf32(v.y); p[2] = f2tf32(v.z); p[3] = f2tf32(v.w);
    }
    __syncthreads();

    int lane = tid & 31, wid = tid >> 5;
    int wm = (wid >> 1) * 16;
    int wn = (wid & 1) * 64;
    int q = lane & 3, g = lane >> 2;
    int half_ = wn >> 6;

    float c[8][4];
#pragma unroll
    for (int nt = 0; nt < 8; nt++)
#pragma unroll
        for (int j = 0; j < 4; j++) c[nt][j] = 0.f;

#pragma unroll
    for (int kt = 0; kt < 16; kt++) {
        int k0 = kt * 8;
        int ar = wm + g;
        uint32_t a0 = xs[ar * XS + k0 + q];
        uint32_t a1 = xs[(ar + 8) * XS + k0 + q];
        uint32_t a2 = xs[ar * XS + k0 + q + 4];
        uint32_t a3 = xs[(ar + 8) * XS + k0 + q + 4];
        const uint32_t* wp = ws + (half_ * 16 + kt) * 8 * 68;
        uint4 b0lo = *(const uint4*)&wp[q * 68 + g * 8];
        uint4 b0hi = *(const uint4*)&wp[q * 68 + g * 8 + 4];
        uint4 b1lo = *(const uint4*)&wp[(q + 4) * 68 + g * 8];
        uint4 b1hi = *(const uint4*)&wp[(q + 4) * 68 + g * 8 + 4];
        uint32_t b0v[8] = {b0lo.x, b0lo.y, b0lo.z, b0lo.w, b0hi.x, b0hi.y, b0hi.z, b0hi.w};
        uint32_t b1v[8] = {b1lo.x, b1lo.y, b1lo.z, b1lo.w, b1hi.x, b1hi.y, b1hi.z, b1hi.w};
#pragma unroll
        for (int nt = 0; nt < 8; nt++) {
            asm volatile(
                "mma.sync.aligned.m16n8k8.row.col.f32.tf32.tf32.f32 "
                "{%0,%1,%2,%3},{%4,%5,%6,%7},{%8,%9},{%0,%1,%2,%3};"
                : "+f"(c[nt][0]), "+f"(c[nt][1]), "+f"(c[nt][2]), "+f"(c[nt][3])
                : "r"(a0), "r"(a1), "r"(a2), "r"(a3), "r"(b0v[nt]), "r"(b1v[nt]));
        }
    }

    int r_lo = row0 + wm + g;
    int r_hi = r_lo + 8;
    float ps_lo[4] = {0, 0, 0, 0}, pd_lo[4] = {0, 0, 0, 0};
    float ps_hi[4] = {0, 0, 0, 0}, pd_hi[4] = {0, 0, 0, 0};
#pragma unroll
    for (int nt = 0; nt < 8; nt++) {
        int col = wn + nt * 8 + 2 * q;
        float as0 = satt[col], as1 = satt[col + 1];
        float ad0 = satt[128 + col], ad1 = satt[128 + col + 1];
        int lh = nt >> 1;
        ps_lo[lh] += c[nt][0] * as0 + c[nt][1] * as1;
        pd_lo[lh] += c[nt][0] * ad0 + c[nt][1] * ad1;
        ps_hi[lh] += c[nt][2] * as0 + c[nt][3] * as1;
        pd_hi[lh] += c[nt][2] * ad0 + c[nt][3] * ad1;
        if (r_lo < N)
            *(__half2*)&g_h1h[r_lo * 128 + col] = __floats2half2_rn(c[nt][0], c[nt][1]);
        if (r_hi < N)
            *(__half2*)&g_h1h[r_hi * 128 + col] = __floats2half2_rn(c[nt][2], c[nt][3]);
    }
#pragma unroll
    for (int lh = 0; lh < 4; lh++) {
#pragma unroll
        for (int o = 1; o <= 2; o <<= 1) {
            ps_lo[lh] += __shfl_xor_sync(0xffffffffu, ps_lo[lh], o);
            pd_lo[lh] += __shfl_xor_sync(0xffffffffu, pd_lo[lh], o);
            ps_hi[lh] += __shfl_xor_sync(0xffffffffu, ps_hi[lh], o);
            pd_hi[lh] += __shfl_xor_sync(0xffffffffu, pd_hi[lh], o);
        }
    }
    if (q == 0) {
        int hb = wn >> 4;
#pragma unroll
        for (int lh = 0; lh < 4; lh++) {
            int h = hb + lh;
            if (r_lo < N) { g_asrc1[r_lo * 8 + h] = ps_lo[lh]; g_adst1[r_lo * 8 + h] = pd_lo[lh]; }
            if (r_hi < N) { g_asrc1[r_hi * 8 + h] = ps_hi[lh]; g_adst1[r_hi * 8 + h] = pd_hi[lh]; }
        }
    }
}

// ---------------- layer2 GEMM (TF32) + fused att2 logits --------------------
__global__ __launch_bounds__(256) void gemm2_tf32_kernel(
    const float* __restrict__ X, const float* __restrict__ W,
    const float* __restrict__ att_src, const float* __restrict__ att_dst,
    float* __restrict__ Y, int N) {
    const int WS2 = 44, XS = 132;
    extern __shared__ float smf[];
    uint32_t* ws = (uint32_t*)smf;                   // 128 x WS2
    uint32_t* xs = (uint32_t*)(smf + 128 * WS2);     // 128 x XS
    float* satt = smf + 128 * WS2 + 128 * XS;        // 80 floats
    int tid = threadIdx.x;

    for (int i = tid; i < 128 * 40; i += 256) {
        int k = i / 40, n = i % 40;
        ws[k * WS2 + n] = f2tf32(W[i]);
    }
    if (tid < 40) satt[tid] = att_src[tid];
    else if (tid < 80) satt[tid] = att_dst[tid - 40];

    int row0 = blockIdx.x * 128;
    for (int i = tid; i < 128 * 32; i += 256) {
        int r = i >> 5, k4 = (i & 31) * 4;
        int row = row0 + r;
        float4 v = (row < N) ? *(const float4*)&X[row * 128 + k4]
                             : make_float4(0.f, 0.f, 0.f, 0.f);
        uint32_t* p = &xs[r * XS + k4];
        p[0] = f2tf32(v.x); p[1] = f2tf32(v.y); p[2] = f2tf32(v.z); p[3] = f2tf32(v.w);
    }
    __syncthreads();

    int lane = tid & 31, wid = tid >> 5;
    int wm = wid * 16;
    int q = lane & 3, g = lane >> 2;

    float c[5][4];
#pragma unroll
    for (int nt = 0; nt < 5; nt++)
#pragma unroll
        for (int j = 0; j < 4; j++) c[nt][j] = 0.f;

#pragma unroll
    for (int kt = 0; kt < 16; kt++) {
        int k0 = kt * 8;
        int ar = wm + g;
        uint32_t a0 = xs[ar * XS + k0 + q];
        uint32_t a1 = xs[(ar + 8) * XS + k0 + q];
        uint32_t a2 = xs[ar * XS + k0 + q + 4];
        uint32_t a3 = xs[(ar + 8) * XS + k0 + q + 4];
#pragma unroll
        for (int nt = 0; nt < 5; nt++) {
            uint32_t b0 = ws[(k0 + q) * WS2 + nt * 8 + g];
            uint32_t b1 = ws[(k0 + q + 4) * WS2 + nt * 8 + g];
            asm volatile(
                "mma.sync.aligned.m16n8k8.row.col.f32.tf32.tf32.f32 "
                "{%0,%1,%2,%3},{%4,%5,%6,%7},{%8,%9},{%0,%1,%2,%3};"
                : "+f"(c[nt][0]), "+f"(c[nt][1]), "+f"(c[nt][2]), "+f"(c[nt][3])
                : "r"(a0), "r"(a1), "r"(a2), "r"(a3), "r"(b0), "r"(b1));
        }
    }

    int r_lo = row0 + wm + g;
    int r_hi = r_lo + 8;
    float ps_lo = 0.f, pd_lo = 0.f, ps_hi = 0.f, pd_hi = 0.f;
#pragma unroll
    for (int nt = 0; nt < 5; nt++) {
        int col = nt * 8 + 2 * q;
        float as0 = satt[col], as1 = satt[col + 1];
        float ad0 = satt[40 + col], ad1 = satt[40 + col + 1];
        ps_lo += c[nt][0] * as0 + c[nt][1] * as1;
        pd_lo += c[nt][0] * ad0 + c[nt][1] * ad1;
        ps_hi += c[nt][2] * as0 + c[nt][3] * as1;
        pd_hi += c[nt][2] * ad0 + c[nt][3] * ad1;
        if (r_lo < N) *(float2*)&Y[r_lo * 40 + col] = make_float2(c[nt][0], c[nt][1]);
        if (r_hi < N) *(float2*)&Y[r_hi * 40 + col] = make_float2(c[nt][2], c[nt][3]);
    }
#pragma unroll
    for (int o = 1; o <= 2; o <<= 1) {
        ps_lo += __shfl_xor_sync(0xffffffffu, ps_lo, o);
        pd_lo += __shfl_xor_sync(0xffffffffu, pd_lo, o);
        ps_hi += __shfl_xor_sync(0xffffffffu, ps_hi, o);
        pd_hi += __shfl_xor_sync(0xffffffffu, pd_hi, o);
    }
    if (q == 0) {
        if (r_lo < N) { g_asrc2[r_lo] = ps_lo; g_adst2[r_lo] = pd_lo; }
        if (r_hi < N) { g_asrc2[r_hi] = ps_hi; g_adst2[r_hi] = pd_hi; }
    }
}

// ---------------- aggregation: single pass, no max (logits bounded) ---------
__global__ void agg1_kernel(const float* __restrict__ bias, int N) {
    int node = (blockIdx.x * blockDim.x + threadIdx.x) >> 5;
    if (node >= N) return;
    int lane = threadIdx.x & 31;
    int h = lane >> 2;
    int beg = g_off[node], end = g_off[node + 1];

    float adst = g_adst1[node * 8 + h];
    float w0 = __expf(lrelu(g_asrc1[node * 8 + h] + adst));   // self-loop
    float denom = w0;
    uint2 raw0 = *(const uint2*)&g_h1h[node * 128 + lane * 4];
    float2 f0a = __half22float2(*(__half2*)&raw0.x);
    float2 f0b = __half22float2(*(__half2*)&raw0.y);
    float4 acc = make_float4(w0 * f0a.x, w0 * f0a.y, w0 * f0b.x, w0 * f0b.y);

#pragma unroll 4
    for (int e = beg; e < end; e++) {
        int s = g_csr[e];
        float wv = __expf(lrelu(g_asrc1[s * 8 + h] + adst));
        uint2 raw = *(const uint2*)&g_h1h[s * 128 + lane * 4];
        float2 fa = __half22float2(*(__half2*)&raw.x);
        float2 fb = __half22float2(*(__half2*)&raw.y);
        denom += wv;
        acc.x = fmaf(wv, fa.x, acc.x);
        acc.y = fmaf(wv, fa.y, acc.y);
        acc.z = fmaf(wv, fb.x, acc.z);
        acc.w = fmaf(wv, fb.y, acc.w);
    }
    float inv = 1.f / (denom + 1e-16f);
    float4 b = *(const float4*)&bias[lane * 4];
    *(float4*)&g_out1[node * 128 + lane * 4] =
        make_float4(fmaf(acc.x, inv, b.x), fmaf(acc.y, inv, b.y),
                    fmaf(acc.z, inv, b.z), fmaf(acc.w, inv, b.w));
}

__global__ void agg2_kernel(const float* __restrict__ bias, float* __restrict__ out, int N) {
    int node = (blockIdx.x * blockDim.x + threadIdx.x) >> 5;
    if (node >= N) return;
    int lane = threadIdx.x & 31;
    int beg = g_off[node], end = g_off[node + 1];

    float adst = g_adst2[node];
    float w0 = __expf(lrelu(g_asrc2[node] + adst));
    float denom = w0;
    float4 acc = make_float4(0.f, 0.f, 0.f, 0.f);
    if (lane < 10) {
        float4 hv = *(const float4*)&g_h2[node * 40 + lane * 4];
        acc = make_float4(w0 * hv.x, w0 * hv.y, w0 * hv.z, w0 * hv.w);
    }

#pragma unroll 4
    for (int e = beg; e < end; e++) {
        int s = g_csr[e];
        float wv = __expf(lrelu(g_asrc2[s] + adst));
        denom += wv;
        if (lane < 10) {
            float4 v = *(const float4*)&g_h2[s * 40 + lane * 4];
            acc.x = fmaf(wv, v.x, acc.x);
            acc.y = fmaf(wv, v.y, acc.y);
            acc.z = fmaf(wv, v.z, acc.z);
            acc.w = fmaf(wv, v.w, acc.w);
        }
    }
    float inv = 1.f / (denom + 1e-16f);
    if (lane < 10) {
        float4 b = *(const float4*)&bias[lane * 4];
        *(float4*)&out[node * 40 + lane * 4] =
            make_float4(fmaf(acc.x, inv, b.x), fmaf(acc.y, inv, b.y),
                        fmaf(acc.z, inv, b.z), fmaf(acc.w, inv, b.w));
    }
}

// ---------------- launch ----------------------------------------------------
extern "C" void kernel_launch(void* const* d_in, const int* in_sizes, int n_in,
                              void* d_out, int out_size) {
    const float* x        = (const float*)d_in[0];
    const int*   ei       = (const int*)d_in[1];
    const float* W1       = (const float*)d_in[2];
    const float* att_src1 = (const float*)d_in[3];
    const float* att_dst1 = (const float*)d_in[4];
    const float* bias1    = (const float*)d_in[5];
    const float* W2       = (const float*)d_in[6];
    const float* att_src2 = (const float*)d_in[7];
    const float* att_dst2 = (const float*)d_in[8];
    const float* bias2    = (const float*)d_in[9];
    float* out = (float*)d_out;

    int N = in_sizes[0] / 128;
    int E = in_sizes[1] / 2;
    const int* src = ei;
    const int* dst = ei + E;

    float *out1p, *h2p;
    int *cntp;
    cudaGetSymbolAddress((void**)&out1p, g_out1);
    cudaGetSymbolAddress((void**)&h2p, g_h2);
    cudaGetSymbolAddress((void**)&cntp, g_cnt);

    int smem1 = (17408 + 64 * 132 + 256) * 4;            // 104448 B
    int smem2 = (128 * 44 + 128 * 132 + 80) * 4;         // 90432 B
    static cudaStream_t s_csr = nullptr;
    static cudaEvent_t ev_fork = nullptr, ev_csr = nullptr;
    static bool init_done = false;
    if (!init_done) {
        cudaFuncSetAttribute(gemm1_tf32_kernel,
                             cudaFuncAttributeMaxDynamicSharedMemorySize, smem1);
        cudaFuncSetAttribute(gemm2_tf32_kernel,
                             cudaFuncAttributeMaxDynamicSharedMemorySize, smem2);
        cudaStreamCreateWithFlags(&s_csr, cudaStreamNonBlocking);
        cudaEventCreateWithFlags(&ev_fork, cudaEventDisableTiming);
        cudaEventCreateWithFlags(&ev_csr, cudaEventDisableTiming);
        init_done = true;
    }

    int eb = (E + 255) / 256;
    int eb4 = ((E + 3) / 4 + 255) / 256;
    int wb = (N + 7) / 8;
    int gb1 = (N + 63) / 64;
    int gb2 = (N + 127) / 128;

    // fork: CSR build on side stream, concurrent with W-prep + gemm1
    cudaEventRecord(ev_fork, 0);
    cudaStreamWaitEvent(s_csr, ev_fork, 0);

    cudaMemsetAsync(cntp, 0, (size_t)N * sizeof(int), s_csr);
    hist_kernel<<<eb4, 256, 0, s_csr>>>(dst, E);
    scan_kernel<<<1, 1024, 0, s_csr>>>(N);
    scatter_kernel<<<eb, 256, 0, s_csr>>>(src, dst, E);
    cudaEventRecord(ev_csr, s_csr);

    prep_w1_kernel<<<64, 256>>>(W1);
    gemm1_tf32_kernel<<<gb1, 256, smem1>>>(x, att_src1, att_dst1, N);

    // join: agg1 needs CSR + gemm1
    cudaStreamWaitEvent(0, ev_csr, 0);
    agg1_kernel<<<wb, 256>>>(bias1, N);

    // layer 2
    gemm2_tf32_kernel<<<gb2, 256, smem2>>>(out1p, W2, att_src2, att_dst2, h2p, N);
    agg2_kernel<<<wb, 256>>>(bias2, out, N);
}